// round 4
// baseline (speedup 1.0000x reference)
#include <cuda_runtime.h>
#include <stdint.h>

// Inputs are int32 (JAX x64 disabled: jnp.int64 -> int32). The reference's
// triple key (h*15000+r)*15000+t therefore WRAPS in int32 arithmetic; we
// replicate that exactly with uint32 math (identical wrap semantics).
//
// Open-addressing hash set: 2^25 x 4B slots = 128MB static device scratch,
// rebuilt every call (deterministic, allocation-free, graph-capturable).
#define TABLE_LOG2 25
#define TABLE_SIZE (1u << TABLE_LOG2)
#define TABLE_MASK (TABLE_SIZE - 1u)
#define EMPTY_SLOT 0xFFFFFFFFu
#define N_ENT 15000u

__device__ unsigned int g_table[TABLE_SIZE];
__device__ int g_has_sentinel;   // does data contain wrapped key 0xFFFFFFFF?

__device__ __forceinline__ uint32_t make_key(uint32_t h, uint32_t r, uint32_t t) {
    return (h * N_ENT + r) * N_ENT + t;   // wraps mod 2^32, same as int32 ref
}

__device__ __forceinline__ uint32_t hash_key(uint32_t x) {
    // murmur3 finalizer (full avalanche on 32 bits)
    x ^= x >> 16; x *= 0x85ebca6bu;
    x ^= x >> 13; x *= 0xc2b2ae35u;
    x ^= x >> 16;
    return x & TABLE_MASK;
}

// ---------------- Pass 1: clear table ----------------
__global__ void clear_table_kernel() {
    uint4* p = reinterpret_cast<uint4*>(g_table);
    const uint32_t n = TABLE_SIZE / 4;          // 8M uint4
    uint32_t i = blockIdx.x * blockDim.x + threadIdx.x;
    const uint32_t stride = gridDim.x * blockDim.x;
    uint4 v; v.x = v.y = v.z = v.w = EMPTY_SLOT;
    for (; i < n; i += stride) p[i] = v;
    if (blockIdx.x == 0 && threadIdx.x == 0) g_has_sentinel = 0;
}

// ---------------- Pass 2: insert data triples ----------------
__global__ void insert_kernel(const int* __restrict__ data, int n) {
    int i = blockIdx.x * blockDim.x + threadIdx.x;
    int stride = gridDim.x * blockDim.x;
    for (; i < n; i += stride) {
        uint32_t h = (uint32_t)data[i];
        uint32_t r = (uint32_t)data[n + i];
        uint32_t t = (uint32_t)data[2 * n + i];
        uint32_t key = make_key(h, r, t);
        if (key == EMPTY_SLOT) { g_has_sentinel = 1; continue; }
        uint32_t slot = hash_key(key);
        while (true) {
            unsigned int prev = atomicCAS(&g_table[slot], EMPTY_SLOT, key);
            if (prev == EMPTY_SLOT || prev == key) break;
            slot = (slot + 1) & TABLE_MASK;
        }
    }
}

// ---------------- Pass 3: probe queries ----------------
__global__ void query_kernel(const int* __restrict__ heads,
                             const int* __restrict__ rels,
                             const int* __restrict__ tails,
                             float* __restrict__ out, int q) {
    int i = blockIdx.x * blockDim.x + threadIdx.x;
    if (i >= q) return;
    uint32_t key = make_key((uint32_t)heads[i], (uint32_t)rels[i], (uint32_t)tails[i]);
    float result;
    if (key == EMPTY_SLOT) {
        result = g_has_sentinel ? 5.0f : -5.0f;
    } else {
        result = -5.0f;
        uint32_t slot = hash_key(key);
        while (true) {
            unsigned int v = __ldg(&g_table[slot]);
            if (v == EMPTY_SLOT) break;              // definite miss
            if (v == key) { result = 5.0f; break; }  // hit
            slot = (slot + 1) & TABLE_MASK;
        }
    }
    out[i] = result;
}

extern "C" void kernel_launch(void* const* d_in, const int* in_sizes, int n_in,
                              void* d_out, int out_size) {
    const int* heads = (const int*)d_in[0];
    const int* rels  = (const int*)d_in[1];
    const int* tails = (const int*)d_in[2];
    const int* data  = (const int*)d_in[3];
    float* out = (float*)d_out;

    const int q = in_sizes[0];
    const int n = in_sizes[3] / 3;

    // Pass 1: clear 128MB table (streaming stores)
    {
        const int threads = 256;
        const int blocks = 148 * 8;   // grid-stride over 8M uint4
        clear_table_kernel<<<blocks, threads>>>();
    }
    // Pass 2: insert n keys (random 32b atomicCAS)
    {
        const int threads = 256;
        int blocks = (n + threads - 1) / threads;
        const int maxb = 148 * 32;
        if (blocks > maxb) blocks = maxb;
        insert_kernel<<<blocks, threads>>>(data, n);
    }
    // Pass 3: probe q queries
    {
        const int threads = 256;
        int blocks = (q + threads - 1) / threads;
        query_kernel<<<blocks, threads>>>(heads, rels, tails, out, q);
    }
}

// round 5
// speedup vs baseline: 1.0042x; 1.0042x over previous
#include <cuda_runtime.h>
#include <stdint.h>

// Inputs are int32 (JAX x64 disabled). Triple key (h*15000+r)*15000+t wraps
// in int32 arithmetic; replicated exactly with uint32 math.
//
// Open-addressing hash set: 2^24 x 4B = 64MB -> fully L2-resident (126MB L2).
// Rebuilt every call (deterministic, allocation-free, graph-capturable).
#define TABLE_LOG2 24
#define TABLE_SIZE (1u << TABLE_LOG2)
#define TABLE_MASK (TABLE_SIZE - 1u)
#define EMPTY_SLOT 0xFFFFFFFFu
#define N_ENT 15000u

__device__ unsigned int g_table[TABLE_SIZE];
__device__ int g_has_sentinel;   // does data contain wrapped key 0xFFFFFFFF?

__device__ __forceinline__ uint32_t make_key(uint32_t h, uint32_t r, uint32_t t) {
    return (h * N_ENT + r) * N_ENT + t;   // wraps mod 2^32 == int32 ref
}

__device__ __forceinline__ uint32_t hash_key(uint32_t x) {
    // murmur3 finalizer (full avalanche), then take low TABLE_LOG2 bits
    x ^= x >> 16; x *= 0x85ebca6bu;
    x ^= x >> 13; x *= 0xc2b2ae35u;
    x ^= x >> 16;
    return x & TABLE_MASK;
}

__device__ __forceinline__ unsigned int ld_l2(const unsigned int* p) {
    unsigned int v;
    asm volatile("ld.global.cg.u32 %0, [%1];" : "=r"(v) : "l"(p));
    return v;
}

// ---------------- Pass 1: clear table ----------------
__global__ void clear_table_kernel() {
    uint4* p = reinterpret_cast<uint4*>(g_table);
    const uint32_t n = TABLE_SIZE / 4;          // 4M uint4
    uint32_t i = blockIdx.x * blockDim.x + threadIdx.x;
    const uint32_t stride = gridDim.x * blockDim.x;
    uint4 v; v.x = v.y = v.z = v.w = EMPTY_SLOT;
    for (; i < n; i += stride) p[i] = v;
    if (blockIdx.x == 0 && threadIdx.x == 0) g_has_sentinel = 0;
}

// ---------------- Pass 2: insert data triples (1 thread / item) ----------------
__global__ void insert_kernel(const int* __restrict__ data, int n) {
    int i = blockIdx.x * blockDim.x + threadIdx.x;
    if (i >= n) return;
    uint32_t h = (uint32_t)data[i];
    uint32_t r = (uint32_t)data[n + i];
    uint32_t t = (uint32_t)data[2 * n + i];
    uint32_t key = make_key(h, r, t);
    if (key == EMPTY_SLOT) { g_has_sentinel = 1; return; }
    uint32_t slot = hash_key(key);
    // load-then-CAS: probe with cheap L2 loads, CAS only on an empty slot
    while (true) {
        unsigned int cur = ld_l2(&g_table[slot]);
        if (cur == key) break;                       // duplicate already in
        if (cur == EMPTY_SLOT) {
            unsigned int prev = atomicCAS(&g_table[slot], EMPTY_SLOT, key);
            if (prev == EMPTY_SLOT || prev == key) break;
            // lost race to a different key -> fall through and advance
        }
        slot = (slot + 1) & TABLE_MASK;
    }
}

// ---------------- Pass 3: probe queries ----------------
__global__ void query_kernel(const int* __restrict__ heads,
                             const int* __restrict__ rels,
                             const int* __restrict__ tails,
                             float* __restrict__ out, int q) {
    int i = blockIdx.x * blockDim.x + threadIdx.x;
    if (i >= q) return;
    uint32_t key = make_key((uint32_t)heads[i], (uint32_t)rels[i], (uint32_t)tails[i]);
    float result;
    if (key == EMPTY_SLOT) {
        result = g_has_sentinel ? 5.0f : -5.0f;
    } else {
        result = -5.0f;
        uint32_t slot = hash_key(key);
        while (true) {
            unsigned int v = ld_l2(&g_table[slot]);
            if (v == EMPTY_SLOT) break;              // definite miss
            if (v == key) { result = 5.0f; break; }  // hit
            slot = (slot + 1) & TABLE_MASK;
        }
    }
    out[i] = result;
}

extern "C" void kernel_launch(void* const* d_in, const int* in_sizes, int n_in,
                              void* d_out, int out_size) {
    const int* heads = (const int*)d_in[0];
    const int* rels  = (const int*)d_in[1];
    const int* tails = (const int*)d_in[2];
    const int* data  = (const int*)d_in[3];
    float* out = (float*)d_out;

    const int q = in_sizes[0];
    const int n = in_sizes[3] / 3;

    // Pass 1: clear 64MB table (streaming 16B stores)
    clear_table_kernel<<<148 * 8, 256>>>();

    // Pass 2: insert n keys, one thread per item (max MLP, L2-resident atomics)
    {
        const int threads = 256;
        int blocks = (n + threads - 1) / threads;
        insert_kernel<<<blocks, threads>>>(data, n);
    }
    // Pass 3: probe q queries
    {
        const int threads = 256;
        int blocks = (q + threads - 1) / threads;
        query_kernel<<<blocks, threads>>>(heads, rels, tails, out, q);
    }
}

// round 6
// speedup vs baseline: 3.2618x; 3.2482x over previous
#include <cuda_runtime.h>
#include <stdint.h>

// Inverted strategy: hash the 100k QUERIES (tiny table), then stream the 10M
// data triples through it, marking found keys. This removes the 10M-atomic
// build of the previous version (the measured bottleneck).
//
// Inputs are int32 (JAX x64 disabled). Triple key (h*15000+r)*15000+t wraps
// in int32 arithmetic; replicated exactly with uint32 math.
//
// Table slot (uint64): EMPTY = all-ones. Stored entry = key (low 32b) | flag
// (bit 32). Stored values are < 2^33, so EMPTY never aliases a real entry --
// the 0xFFFFFFFF wrapped-key sentinel problem vanishes.
#define QT_LOG2 19
#define QT_SIZE (1u << QT_LOG2)
#define QT_MASK (QT_SIZE - 1u)
#define EMPTY64 0xFFFFFFFFFFFFFFFFull
#define FOUND_BIT (1ull << 32)
#define N_ENT 15000u

__device__ unsigned long long g_qtable[QT_SIZE];   // 4MB, L2-resident

__device__ __forceinline__ uint32_t make_key(uint32_t h, uint32_t r, uint32_t t) {
    return (h * N_ENT + r) * N_ENT + t;   // wraps mod 2^32 == int32 reference
}

__device__ __forceinline__ uint32_t hash_key(uint32_t x) {
    x ^= x >> 16; x *= 0x85ebca6bu;
    x ^= x >> 13; x *= 0xc2b2ae35u;
    x ^= x >> 16;
    return x & QT_MASK;
}

__device__ __forceinline__ unsigned long long ld_cg64(const unsigned long long* p) {
    unsigned long long v;
    asm volatile("ld.global.cg.u64 %0, [%1];" : "=l"(v) : "l"(p));
    return v;
}
__device__ __forceinline__ void st_cg64(unsigned long long* p, unsigned long long v) {
    asm volatile("st.global.cg.u64 [%0], %1;" :: "l"(p), "l"(v));
}

// ---- Pass A: clear the 4MB query table ----
__global__ void clear_qtable_kernel() {
    ulonglong2* p = reinterpret_cast<ulonglong2*>(g_qtable);
    const uint32_t n = QT_SIZE / 2;
    uint32_t i = blockIdx.x * blockDim.x + threadIdx.x;
    const uint32_t stride = gridDim.x * blockDim.x;
    ulonglong2 v; v.x = EMPTY64; v.y = EMPTY64;
    for (; i < n; i += stride) p[i] = v;
}

// ---- Pass B: insert query keys (dedup via CAS) ----
__global__ void insert_queries_kernel(const int* __restrict__ heads,
                                      const int* __restrict__ rels,
                                      const int* __restrict__ tails, int q) {
    int i = blockIdx.x * blockDim.x + threadIdx.x;
    if (i >= q) return;
    uint32_t key = make_key((uint32_t)heads[i], (uint32_t)rels[i], (uint32_t)tails[i]);
    uint32_t slot = hash_key(key);
    while (true) {
        unsigned long long v = ld_cg64(&g_qtable[slot]);
        if ((uint32_t)v == key && v != EMPTY64) break;        // dup already in
        if (v == EMPTY64) {
            unsigned long long prev =
                atomicCAS(&g_qtable[slot], EMPTY64, (unsigned long long)key);
            if (prev == EMPTY64 || (uint32_t)prev == key) break;
        }
        slot = (slot + 1) & QT_MASK;
    }
}

// ---- Pass C: stream data triples, mark found query keys ----
__global__ void mark_kernel(const int* __restrict__ data, int n) {
    int i = blockIdx.x * blockDim.x + threadIdx.x;
    if (i >= n) return;
    uint32_t key = make_key((uint32_t)data[i], (uint32_t)data[n + i],
                            (uint32_t)data[2 * n + i]);
    uint32_t slot = hash_key(key);
    while (true) {
        unsigned long long v = ld_cg64(&g_qtable[slot]);
        if (v == EMPTY64) break;                               // not a query key
        if ((uint32_t)v == key) {
            // benign race: all writers store the identical packed value
            if (!(v & FOUND_BIT))
                st_cg64(&g_qtable[slot], (unsigned long long)key | FOUND_BIT);
            break;
        }
        slot = (slot + 1) & QT_MASK;
    }
}

// ---- Pass D: resolve each query from the flag bit ----
__global__ void resolve_kernel(const int* __restrict__ heads,
                               const int* __restrict__ rels,
                               const int* __restrict__ tails,
                               float* __restrict__ out, int q) {
    int i = blockIdx.x * blockDim.x + threadIdx.x;
    if (i >= q) return;
    uint32_t key = make_key((uint32_t)heads[i], (uint32_t)rels[i], (uint32_t)tails[i]);
    uint32_t slot = hash_key(key);
    float result = -5.0f;
    while (true) {
        unsigned long long v = ld_cg64(&g_qtable[slot]);
        if (v == EMPTY64) break;                               // should not happen
        if ((uint32_t)v == key) {
            result = (v & FOUND_BIT) ? 5.0f : -5.0f;
            break;
        }
        slot = (slot + 1) & QT_MASK;
    }
    out[i] = result;
}

extern "C" void kernel_launch(void* const* d_in, const int* in_sizes, int n_in,
                              void* d_out, int out_size) {
    const int* heads = (const int*)d_in[0];
    const int* rels  = (const int*)d_in[1];
    const int* tails = (const int*)d_in[2];
    const int* data  = (const int*)d_in[3];
    float* out = (float*)d_out;

    const int q = in_sizes[0];
    const int n = in_sizes[3] / 3;
    const int threads = 256;

    // A: clear 4MB table
    clear_qtable_kernel<<<148 * 4, threads>>>();
    // B: insert 100k query keys
    insert_queries_kernel<<<(q + threads - 1) / threads, threads>>>(heads, rels, tails, q);
    // C: stream 10M data triples through the table
    mark_kernel<<<(n + threads - 1) / threads, threads>>>(data, n);
    // D: write +/-5 per query
    resolve_kernel<<<(q + threads - 1) / threads, threads>>>(heads, rels, tails, out, q);
}